// round 12
// baseline (speedup 1.0000x reference)
#include <cuda_runtime.h>
#include <cuda_bf16.h>
#include <math.h>
#include <cstdint>

#define NN 100000
#define EE 1600000
#define HH 128
#define HD2 256

// ---------------- scratch (__device__ globals) -------------------------------
__device__ __nv_bfloat16 g_xh [(size_t)NN * HH];
__device__ __nv_bfloat16 g_xl [(size_t)NN * HH];
__device__ float         g_t  [(size_t)NN * HH];
__device__ __nv_bfloat16 g_h1h[(size_t)NN * HD2];
__device__ __nv_bfloat16 g_h1l[(size_t)NN * HD2];
__device__ float g_s[2][NN];
__device__ int   g_rp  [NN + 1];
__device__ int   g_cnt [NN];
__device__ int   g_cols[EE];
__device__ float g_vals[EE];

#define WT_W(i)  ((size_t)(i) * 16384)
#define WT_M1    ((size_t)8 * 16384)
#define WT_M2    (WT_M1 + 32768)
#define WT_TOTAL (WT_M2 + 65536)
__device__ __nv_bfloat16 g_wth[WT_TOTAL];
__device__ __nv_bfloat16 g_wtl[WT_TOTAL];

// ---------------- helpers ----------------------------------------------------
__device__ __forceinline__ uint32_t smem_u32(const void* p) {
    uint32_t a;
    asm("{ .reg .u64 t; cvta.to.shared.u64 t, %1; cvt.u32.u64 %0, t; }" : "=r"(a) : "l"(p));
    return a;
}
__device__ __forceinline__ void ldmx4(uint32_t* r, uint32_t addr) {
    asm volatile("ldmatrix.sync.aligned.m8n8.x4.shared.b16 {%0,%1,%2,%3}, [%4];"
                 : "=r"(r[0]), "=r"(r[1]), "=r"(r[2]), "=r"(r[3]) : "r"(addr));
}
__device__ __forceinline__ void mma_bf16(float* c, const uint32_t* a, uint32_t b0, uint32_t b1) {
    asm volatile(
        "mma.sync.aligned.m16n8k16.row.col.f32.bf16.bf16.f32 "
        "{%0,%1,%2,%3}, {%4,%5,%6,%7}, {%8,%9}, {%0,%1,%2,%3};"
        : "+f"(c[0]), "+f"(c[1]), "+f"(c[2]), "+f"(c[3])
        : "r"(a[0]), "r"(a[1]), "r"(a[2]), "r"(a[3]), "r"(b0), "r"(b1));
}
__device__ __forceinline__ void cpa16(uint32_t dst, const void* src, int nbytes) {
    asm volatile("cp.async.cg.shared.global [%0], [%1], 16, %2;"
                 :: "r"(dst), "l"(src), "r"(nbytes) : "memory");
}
__device__ __forceinline__ void pack_hl(float a, float b, uint32_t& hu, uint32_t& lu) {
    __nv_bfloat16 ha = __float2bfloat16(a), hb = __float2bfloat16(b);
    __nv_bfloat16 la = __float2bfloat16(a - __bfloat162float(ha));
    __nv_bfloat16 lb = __float2bfloat16(b - __bfloat162float(hb));
    hu = (uint32_t)__bfloat16_as_ushort(ha) | ((uint32_t)__bfloat16_as_ushort(hb) << 16);
    lu = (uint32_t)__bfloat16_as_ushort(la) | ((uint32_t)__bfloat16_as_ushort(lb) << 16);
}

// ---------------- preprocessing ------------------------------------------------
struct ConvSrcs { const float* p[10]; };

__global__ void conv_all_kernel(ConvSrcs srcs, __nv_bfloat16* __restrict__ oh,
                                __nv_bfloat16* __restrict__ ol, int* __restrict__ cnt) {
    int gid = blockIdx.x * blockDim.x + threadIdx.x;
    if (gid < (int)WT_TOTAL) {
        const float* W; int local, K, Ncol;
        if (gid < 131072)               { W = srcs.p[gid >> 14]; local = gid & 16383;            K = HH;  Ncol = HH;  }
        else if (gid < 131072 + 32768)  { W = srcs.p[8];         local = gid - 131072;           K = HH;  Ncol = HD2; }
        else                            { W = srcs.p[9];         local = gid - (131072 + 32768); K = HD2; Ncol = HD2; }
        int n = local / K, k = local - n * K;
        float v = W[(size_t)k * Ncol + n];
        __nv_bfloat16 h = __float2bfloat16(v);
        oh[gid] = h;
        ol[gid] = __float2bfloat16(v - __bfloat162float(h));
    } else {
        int j = gid - (int)WT_TOTAL;
        if (j < NN) cnt[j] = 0;
    }
}

__global__ void zero_int_kernel(int* __restrict__ p, int n) {
    int i = blockIdx.x * blockDim.x + threadIdx.x;
    if (i < n) p[i] = 0;
}

__global__ void hist_kernel(const int* __restrict__ rows, int* __restrict__ cnt, int nE) {
    int e = blockIdx.x * blockDim.x + threadIdx.x;
    if (e < nE) atomicAdd(&cnt[rows[e]], 1);
}

__global__ void scan_kernel(const int* __restrict__ cnt, int* __restrict__ rp,
                            int* __restrict__ cur, int n) {
    __shared__ int sdata[1024];
    __shared__ int carry;
    int tid = threadIdx.x;
    if (tid == 0) { carry = 0; rp[0] = 0; }
    __syncthreads();
    for (int base = 0; base < n; base += 1024) {
        int i = base + tid;
        int v = (i < n) ? cnt[i] : 0;
        sdata[tid] = v;
        __syncthreads();
        #pragma unroll
        for (int o = 1; o < 1024; o <<= 1) {
            int t = sdata[tid];
            if (tid >= o) t += sdata[tid - o];
            __syncthreads();
            sdata[tid] = t;
            __syncthreads();
        }
        if (i < n) {
            int incl = carry + sdata[tid];
            rp[i + 1] = incl;
            cur[i] = incl - v;
        }
        __syncthreads();
        if (tid == 0) carry += sdata[1023];
        __syncthreads();
    }
}

__global__ void scatter_kernel(const int* __restrict__ rows, const int* __restrict__ cols,
                               const float* __restrict__ vals, int* __restrict__ cur,
                               int* __restrict__ cs, float* __restrict__ vs, int nE,
                               float* __restrict__ s, const float* __restrict__ b3, int M) {
    int e = blockIdx.x * blockDim.x + threadIdx.x;
    if (e < M) s[e] = 9.0f * b3[0];
    if (e >= nE) return;
    int pos = atomicAdd(&cur[rows[e]], 1);
    cs[pos] = cols[e];
    vs[pos] = vals[e];
}

// ---------------- CSR SpMM fused relu(+norm) -> split bf16 -------------------
__global__ void spmm_csr_kernel(const int* __restrict__ rp, const int* __restrict__ cs,
                                const float* __restrict__ vs, const float* __restrict__ xin,
                                __nv_bfloat16* __restrict__ xh, __nv_bfloat16* __restrict__ xl,
                                int M, int do_norm) {
    long long idx = (long long)blockIdx.x * blockDim.x + threadIdx.x;
    int row = (int)(idx >> 5);
    if (row >= M) return;
    int lane = (int)(idx & 31);
    int s = __ldg(rp + row), e = __ldg(rp + row + 1);
    float ax = 0.f, ay = 0.f, az = 0.f, aw = 0.f;
    for (int j = s; j < e; j++) {
        int c = __ldg(cs + j);
        float v = __ldg(vs + j);
        float4 xv = *(const float4*)(xin + (size_t)c * HH + lane * 4);
        ax += v * xv.x; ay += v * xv.y; az += v * xv.z; aw += v * xv.w;
    }
    ax = fmaxf(ax, 0.f); ay = fmaxf(ay, 0.f);
    az = fmaxf(az, 0.f); aw = fmaxf(aw, 0.f);
    if (do_norm) {
        float ss = ax * ax + ay * ay + az * az + aw * aw;
        #pragma unroll
        for (int o = 16; o; o >>= 1) ss += __shfl_xor_sync(0xffffffffu, ss, o);
        float inv = 1.0f / fmaxf(sqrtf(ss), 1e-12f);
        ax *= inv; ay *= inv; az *= inv; aw *= inv;
    }
    uint2 hv, lv;
    pack_hl(ax, ay, hv.x, lv.x);
    pack_hl(az, aw, hv.y, lv.y);
    size_t off = (size_t)row * HH + lane * 4;
    *(uint2*)(xh + off) = hv;
    *(uint2*)(xl + off) = lv;
}

__global__ void mul_kernel(const float* __restrict__ a, const float* __restrict__ b,
                           float* __restrict__ out, int M) {
    int i = blockIdx.x * blockDim.x + threadIdx.x;
    if (i < M) out[i] = a[i] * b[i];
}

// ---------------- pipelined mma.sync GEMM -------------------------------------
// 3-term Markidis bf16 split. BM=128,BN=128,BK=32; 8 warps (2x4).
// 4-stage cp.async pipeline, one __syncthreads per chunk, frag double-buffer.
// mode 0 (fused m1+w): blockIdx.y < ny1 -> B1 (m1), relu+bias1, split write Ch/Cl [Ncol1]
//                      blockIdx.y ==ny1 -> B2 (w), raw fp32 write C2 [Ncol2]
// mode 1 (m2 scoring): B1 (m2), epilogue relu(acc+bias1) dot m3s -> atomicAdd(sc)
#define BK 32
#define LDP 40
#define STG_ELEMS (128 * LDP)
#define NSTG 4
#define GEMM_SMEM (NSTG * 4 * STG_ELEMS * 2)   // 163840 B

__global__ void __launch_bounds__(256, 1) tc_gemm_kernel(
    const __nv_bfloat16* __restrict__ Ah, const __nv_bfloat16* __restrict__ Al,
    const __nv_bfloat16* __restrict__ B1h, const __nv_bfloat16* __restrict__ B1l,
    int ny1, int Ncol1, const float* __restrict__ bias1,
    const __nv_bfloat16* __restrict__ B2h, const __nv_bfloat16* __restrict__ B2l,
    float* __restrict__ C2, int Ncol2,
    __nv_bfloat16* __restrict__ Ch, __nv_bfloat16* __restrict__ Cl,
    const float* __restrict__ m3s, float* __restrict__ sc,
    int M, int K, int mode)
{
    extern __shared__ __align__(16) uint16_t smem[];
    const int tid = threadIdx.x;
    const int wid = tid >> 5, lane = tid & 31;
    const int mw = wid >> 2, nw = wid & 3;
    const int row0 = blockIdx.x * 128;
    const bool isW = (mode == 0) && ((int)blockIdx.y == ny1);
    const __nv_bfloat16* Bh = isW ? B2h : B1h;
    const __nv_bfloat16* Bl = isW ? B2l : B1l;
    const int n0 = isW ? 0 : blockIdx.y * 128;

    float acc[4][4][4] = {};
    const uint32_t sbase = smem_u32(smem);
    auto abase = [&](int stage, int arr) {
        return sbase + (uint32_t)(((stage << 2) + arr) * STG_ELEMS * 2);
    };

    auto load_chunk = [&](int c, int stage) {
        const int k0 = c * BK;
        #pragma unroll
        for (int i = 0; i < 2; i++) {
            int idx = tid + i * 256;
            int r = idx >> 2, q = idx & 3;
            uint32_t doff = (uint32_t)(r * LDP + q * 8) * 2;
            int grow = row0 + r;
            int pa = (grow < M) ? 16 : 0;
            int ga = grow < M ? grow : (M - 1);
            cpa16(abase(stage, 0) + doff, Ah + (size_t)ga * K + k0 + q * 8, pa);
            cpa16(abase(stage, 1) + doff, Al + (size_t)ga * K + k0 + q * 8, pa);
            cpa16(abase(stage, 2) + doff, Bh + (size_t)(n0 + r) * K + k0 + q * 8, 16);
            cpa16(abase(stage, 3) + doff, Bl + (size_t)(n0 + r) * K + k0 + q * 8, 16);
        }
    };

    const int a_row_sel = lane & 15;
    const int a_k_sel   = (lane >> 4) * 8;
    const int b_row_sel = (lane & 7) + ((lane >> 4) << 3);
    const int b_k_sel   = ((lane >> 3) & 1) * 8;

    uint32_t ah[2][4][4], al[2][4][4], bh[2][2][4], bl[2][2][4];
    auto load_frags = [&](int buf, uint32_t sAh, uint32_t sAl, uint32_t sBh,
                          uint32_t sBl, int koff) {
        #pragma unroll
        for (int mi = 0; mi < 4; mi++) {
            uint32_t off = (uint32_t)((mw * 64 + mi * 16 + a_row_sel) * LDP
                                      + koff + a_k_sel) * 2;
            ldmx4(ah[buf][mi], sAh + off);
            ldmx4(al[buf][mi], sAl + off);
        }
        #pragma unroll
        for (int p = 0; p < 2; p++) {
            uint32_t off = (uint32_t)((nw * 32 + p * 16 + b_row_sel) * LDP
                                      + koff + b_k_sel) * 2;
            ldmx4(bh[buf][p], sBh + off);
            ldmx4(bl[buf][p], sBl + off);
        }
    };
    auto run_mmas = [&](int buf) {
        #pragma unroll
        for (int mi = 0; mi < 4; mi++) {
            #pragma unroll
            for (int ni = 0; ni < 4; ni++) {
                uint32_t b0h = bh[buf][ni >> 1][(ni & 1) * 2];
                uint32_t b1h = bh[buf][ni >> 1][(ni & 1) * 2 + 1];
                uint32_t b0l = bl[buf][ni >> 1][(ni & 1) * 2];
                uint32_t b1l = bl[buf][ni >> 1][(ni & 1) * 2 + 1];
                mma_bf16(acc[mi][ni], ah[buf][mi], b0h, b1h);
                mma_bf16(acc[mi][ni], ah[buf][mi], b0l, b1l);
                mma_bf16(acc[mi][ni], al[buf][mi], b0h, b1h);
            }
        }
    };

    const int nchunks = K / BK;
    load_chunk(0, 0);
    asm volatile("cp.async.commit_group;" ::: "memory");
    if (nchunks > 1) load_chunk(1, 1);
    asm volatile("cp.async.commit_group;" ::: "memory");

    for (int c = 0; c < nchunks; c++) {
        if (c + 2 < nchunks) load_chunk(c + 2, (c + 2) & (NSTG - 1));
        asm volatile("cp.async.commit_group;" ::: "memory");
        asm volatile("cp.async.wait_group 2;" ::: "memory");
        __syncthreads();
        const int st = c & (NSTG - 1);
        const uint32_t sAh = abase(st, 0), sAl = abase(st, 1);
        const uint32_t sBh = abase(st, 2), sBl = abase(st, 3);
        load_frags(0, sAh, sAl, sBh, sBl, 0);
        load_frags(1, sAh, sAl, sBh, sBl, 16);
        run_mmas(0);
        run_mmas(1);
    }

    const int mrow = row0 + mw * 64 + (lane >> 2);
    const int ncol = nw * 32 + (lane & 3) * 2;   // local within 128-tile

    if (mode == 1) {  // fused scoring
        #pragma unroll
        for (int mi = 0; mi < 4; mi++) {
            int r_lo = mrow + mi * 16;
            int r_hi = r_lo + 8;
            float plo = 0.f, phi = 0.f;
            #pragma unroll
            for (int ni = 0; ni < 4; ni++) {
                int col = n0 + ncol + ni * 8;
                float m30 = __ldg(m3s + col), m31 = __ldg(m3s + col + 1);
                float b0 = __ldg(bias1 + col), b1 = __ldg(bias1 + col + 1);
                plo += fmaxf(acc[mi][ni][0] + b0, 0.f) * m30
                     + fmaxf(acc[mi][ni][1] + b1, 0.f) * m31;
                phi += fmaxf(acc[mi][ni][2] + b0, 0.f) * m30
                     + fmaxf(acc[mi][ni][3] + b1, 0.f) * m31;
            }
            plo += __shfl_xor_sync(0xffffffffu, plo, 1);
            plo += __shfl_xor_sync(0xffffffffu, plo, 2);
            phi += __shfl_xor_sync(0xffffffffu, phi, 1);
            phi += __shfl_xor_sync(0xffffffffu, phi, 2);
            if ((lane & 3) == 0) {
                if (r_lo < M) atomicAdd(sc + r_lo, plo);
                if (r_hi < M) atomicAdd(sc + r_hi, phi);
            }
        }
        return;
    }

    if (!isW) {  // m1 part: relu + bf16 hi/lo split write
        #pragma unroll
        for (int mi = 0; mi < 4; mi++) {
            int r_lo = mrow + mi * 16;
            int r_hi = r_lo + 8;
            #pragma unroll
            for (int ni = 0; ni < 4; ni++) {
                int col = n0 + ncol + ni * 8;
                float b0 = __ldg(bias1 + col), b1 = __ldg(bias1 + col + 1);
                float v0 = fmaxf(acc[mi][ni][0] + b0, 0.f);
                float v1 = fmaxf(acc[mi][ni][1] + b1, 0.f);
                float v2 = fmaxf(acc[mi][ni][2] + b0, 0.f);
                float v3 = fmaxf(acc[mi][ni][3] + b1, 0.f);
                uint32_t hu, lu;
                if (r_lo < M) {
                    pack_hl(v0, v1, hu, lu);
                    *(uint32_t*)(Ch + (size_t)r_lo * Ncol1 + col) = hu;
                    *(uint32_t*)(Cl + (size_t)r_lo * Ncol1 + col) = lu;
                }
                if (r_hi < M) {
                    pack_hl(v2, v3, hu, lu);
                    *(uint32_t*)(Ch + (size_t)r_hi * Ncol1 + col) = hu;
                    *(uint32_t*)(Cl + (size_t)r_hi * Ncol1 + col) = lu;
                }
            }
        }
        return;
    }

    // w part: raw fp32 write to C2
    #pragma unroll
    for (int mi = 0; mi < 4; mi++) {
        int r_lo = mrow + mi * 16;
        int r_hi = r_lo + 8;
        #pragma unroll
        for (int ni = 0; ni < 4; ni++) {
            int col = ncol + ni * 8;
            if (r_lo < M) *(float2*)(C2 + (size_t)r_lo * Ncol2 + col) =
                make_float2(acc[mi][ni][0], acc[mi][ni][1]);
            if (r_hi < M) *(float2*)(C2 + (size_t)r_hi * Ncol2 + col) =
                make_float2(acc[mi][ni][2], acc[mi][ni][3]);
        }
    }
}

// ---------------- launch -----------------------------------------------------
extern "C" void kernel_launch(void* const* d_in, const int* in_sizes, int n_in,
                              void* d_out, int out_size) {
    const int*   adjr[2] = {(const int*)d_in[0], (const int*)d_in[3]};
    const int*   adjc[2] = {(const int*)d_in[1], (const int*)d_in[4]};
    const float* adjv[2] = {(const float*)d_in[2], (const float*)d_in[5]};
    const float* w1 = (const float*)d_in[6];
    const float* m1 = (const float*)d_in[15];
    const float* b1 = (const float*)d_in[16];
    const float* m2 = (const float*)d_in[17];
    const float* b2 = (const float*)d_in[18];
    const float* m3 = (const float*)d_in[19];
    const float* b3 = (const float*)d_in[20];
    float* out = (float*)d_out;

    const int E = in_sizes[0];
    const int M = in_sizes[6] / HH;

    __nv_bfloat16 *xh, *xl, *h1h, *h1l, *wth, *wtl;
    float *gt, *csv;
    float (*gs)[NN];
    int *rp, *cnt, *csc;
    cudaGetSymbolAddress((void**)&xh,  g_xh);
    cudaGetSymbolAddress((void**)&xl,  g_xl);
    cudaGetSymbolAddress((void**)&gt,  g_t);
    cudaGetSymbolAddress((void**)&h1h, g_h1h);
    cudaGetSymbolAddress((void**)&h1l, g_h1l);
    cudaGetSymbolAddress((void**)&gs,  g_s);
    cudaGetSymbolAddress((void**)&rp,  g_rp);
    cudaGetSymbolAddress((void**)&cnt, g_cnt);
    cudaGetSymbolAddress((void**)&csc, g_cols);
    cudaGetSymbolAddress((void**)&csv, g_vals);
    cudaGetSymbolAddress((void**)&wth, g_wth);
    cudaGetSymbolAddress((void**)&wtl, g_wtl);

    cudaFuncSetAttribute(tc_gemm_kernel,
                         cudaFuncAttributeMaxDynamicSharedMemorySize, GEMM_SMEM);

    ConvSrcs cs;
    for (int i = 0; i < 8; i++) cs.p[i] = (const float*)d_in[7 + i];
    cs.p[8] = m1; cs.p[9] = m2;
    {
        int tot = (int)WT_TOTAL + NN;
        conv_all_kernel<<<(tot + 255) / 256, 256>>>(cs, wth, wtl, cnt);
    }

    const int warpBlocks = (int)(((long long)M * 32 + 255) / 256);
    const int eBlocks = (E + 255) / 256;
    const int nBlocks = (M + 255) / 256;
    const int mtiles = (M + 127) / 128;

    for (int b = 0; b < 2; b++) {
        if (b) zero_int_kernel<<<nBlocks, 256>>>(cnt, M);
        hist_kernel<<<eBlocks, 256>>>(adjr[b], cnt, E);
        scan_kernel<<<1, 1024>>>(cnt, rp, cnt, M);
        scatter_kernel<<<eBlocks, 256>>>(adjr[b], adjc[b], adjv[b], cnt, csc, csv,
                                         E, gs[b], b3, M);
        spmm_csr_kernel<<<warpBlocks, 256>>>(rp, csc, csv, w1, xh, xl, M, 1);

        for (int L = 0; L <= 8; L++) {
            // fused m1 (+ wL when L<8): A = x
            dim3 gf(mtiles, (L < 8) ? 3 : 2);
            tc_gemm_kernel<<<gf, 256, GEMM_SMEM>>>(
                xh, xl,
                wth + WT_M1, wtl + WT_M1, 2, HD2, b1,
                (L < 8) ? wth + WT_W(L) : nullptr,
                (L < 8) ? wtl + WT_W(L) : nullptr, gt, HH,
                h1h, h1l, nullptr, nullptr, M, HH, 0);
            // m2 scoring
            dim3 gm(mtiles, 2);
            tc_gemm_kernel<<<gm, 256, GEMM_SMEM>>>(
                h1h, h1l,
                wth + WT_M2, wtl + WT_M2, 2, HD2, b2,
                nullptr, nullptr, nullptr, 0,
                nullptr, nullptr, m3, gs[b], M, HD2, 1);
            if (L < 8)
                spmm_csr_kernel<<<warpBlocks, 256>>>(rp, csc, csv, gt, xh, xl, M,
                                                     (L + 1 < 8) ? 1 : 0);
        }
    }

    mul_kernel<<<nBlocks, 256>>>(gs[0], gs[1], out, M);
}

// round 13
// speedup vs baseline: 1.0043x; 1.0043x over previous
#include <cuda_runtime.h>
#include <cuda_bf16.h>
#include <math.h>
#include <cstdint>

#define NN 100000
#define EE 1600000
#define HH 128
#define HD2 256

// ---------------- scratch (__device__ globals) -------------------------------
__device__ __nv_bfloat16 g_xh [(size_t)NN * HH];
__device__ __nv_bfloat16 g_xl [(size_t)NN * HH];
__device__ float         g_t  [(size_t)NN * HH];
__device__ __nv_bfloat16 g_h1h[(size_t)NN * HD2];
__device__ __nv_bfloat16 g_h1l[(size_t)NN * HD2];
__device__ float g_s[2][NN];
__device__ int   g_rp  [NN + 1];
__device__ int   g_cnt [NN];
__device__ int   g_cols[EE];
__device__ float g_vals[EE];

#define WT_W(i)  ((size_t)(i) * 16384)
#define WT_M1    ((size_t)8 * 16384)
#define WT_M2    (WT_M1 + 32768)
#define WT_TOTAL (WT_M2 + 65536)
__device__ __nv_bfloat16 g_wth[WT_TOTAL];
__device__ __nv_bfloat16 g_wtl[WT_TOTAL];

// ---------------- helpers ----------------------------------------------------
__device__ __forceinline__ uint32_t smem_u32(const void* p) {
    uint32_t a;
    asm("{ .reg .u64 t; cvta.to.shared.u64 t, %1; cvt.u32.u64 %0, t; }" : "=r"(a) : "l"(p));
    return a;
}
__device__ __forceinline__ void ldmx4(uint32_t* r, uint32_t addr) {
    asm volatile("ldmatrix.sync.aligned.m8n8.x4.shared.b16 {%0,%1,%2,%3}, [%4];"
                 : "=r"(r[0]), "=r"(r[1]), "=r"(r[2]), "=r"(r[3]) : "r"(addr));
}
__device__ __forceinline__ void mma_bf16(float* c, const uint32_t* a, uint32_t b0, uint32_t b1) {
    asm volatile(
        "mma.sync.aligned.m16n8k16.row.col.f32.bf16.bf16.f32 "
        "{%0,%1,%2,%3}, {%4,%5,%6,%7}, {%8,%9}, {%0,%1,%2,%3};"
        : "+f"(c[0]), "+f"(c[1]), "+f"(c[2]), "+f"(c[3])
        : "r"(a[0]), "r"(a[1]), "r"(a[2]), "r"(a[3]), "r"(b0), "r"(b1));
}
__device__ __forceinline__ void cpa16(uint32_t dst, const void* src, int nbytes) {
    asm volatile("cp.async.cg.shared.global [%0], [%1], 16, %2;"
                 :: "r"(dst), "l"(src), "r"(nbytes) : "memory");
}
__device__ __forceinline__ void pack_hl(float a, float b, uint32_t& hu, uint32_t& lu) {
    __nv_bfloat16 ha = __float2bfloat16(a), hb = __float2bfloat16(b);
    __nv_bfloat16 la = __float2bfloat16(a - __bfloat162float(ha));
    __nv_bfloat16 lb = __float2bfloat16(b - __bfloat162float(hb));
    hu = (uint32_t)__bfloat16_as_ushort(ha) | ((uint32_t)__bfloat16_as_ushort(hb) << 16);
    lu = (uint32_t)__bfloat16_as_ushort(la) | ((uint32_t)__bfloat16_as_ushort(lb) << 16);
}

// ---------------- preprocessing ------------------------------------------------
struct ConvSrcs { const float* p[10]; };

__global__ void conv_all_kernel(ConvSrcs srcs, __nv_bfloat16* __restrict__ oh,
                                __nv_bfloat16* __restrict__ ol, int* __restrict__ cnt) {
    int gid = blockIdx.x * blockDim.x + threadIdx.x;
    if (gid < (int)WT_TOTAL) {
        const float* W; int local, K, Ncol;
        if (gid < 131072)               { W = srcs.p[gid >> 14]; local = gid & 16383;            K = HH;  Ncol = HH;  }
        else if (gid < 131072 + 32768)  { W = srcs.p[8];         local = gid - 131072;           K = HH;  Ncol = HD2; }
        else                            { W = srcs.p[9];         local = gid - (131072 + 32768); K = HD2; Ncol = HD2; }
        int n = local / K, k = local - n * K;
        float v = W[(size_t)k * Ncol + n];
        __nv_bfloat16 h = __float2bfloat16(v);
        oh[gid] = h;
        ol[gid] = __float2bfloat16(v - __bfloat162float(h));
    } else {
        int j = gid - (int)WT_TOTAL;
        if (j < NN) cnt[j] = 0;
    }
}

__global__ void zero_int_kernel(int* __restrict__ p, int n) {
    int i = blockIdx.x * blockDim.x + threadIdx.x;
    if (i < n) p[i] = 0;
}

__global__ void hist_kernel(const int* __restrict__ rows, int* __restrict__ cnt, int nE) {
    int e = blockIdx.x * blockDim.x + threadIdx.x;
    if (e < nE) atomicAdd(&cnt[rows[e]], 1);
}

__global__ void scan_kernel(const int* __restrict__ cnt, int* __restrict__ rp,
                            int* __restrict__ cur, int n) {
    __shared__ int sdata[1024];
    __shared__ int carry;
    int tid = threadIdx.x;
    if (tid == 0) { carry = 0; rp[0] = 0; }
    __syncthreads();
    for (int base = 0; base < n; base += 1024) {
        int i = base + tid;
        int v = (i < n) ? cnt[i] : 0;
        sdata[tid] = v;
        __syncthreads();
        #pragma unroll
        for (int o = 1; o < 1024; o <<= 1) {
            int t = sdata[tid];
            if (tid >= o) t += sdata[tid - o];
            __syncthreads();
            sdata[tid] = t;
            __syncthreads();
        }
        if (i < n) {
            int incl = carry + sdata[tid];
            rp[i + 1] = incl;
            cur[i] = incl - v;
        }
        __syncthreads();
        if (tid == 0) carry += sdata[1023];
        __syncthreads();
    }
}

__global__ void scatter_kernel(const int* __restrict__ rows, const int* __restrict__ cols,
                               const float* __restrict__ vals, int* __restrict__ cur,
                               int* __restrict__ cs, float* __restrict__ vs, int nE,
                               float* __restrict__ s, const float* __restrict__ b3, int M) {
    int e = blockIdx.x * blockDim.x + threadIdx.x;
    if (e < M) s[e] = 9.0f * b3[0];
    if (e >= nE) return;
    int pos = atomicAdd(&cur[rows[e]], 1);
    cs[pos] = cols[e];
    vs[pos] = vals[e];
}

// ---------------- CSR SpMM fused relu(+norm) -> split bf16 -------------------
__global__ void spmm_csr_kernel(const int* __restrict__ rp, const int* __restrict__ cs,
                                const float* __restrict__ vs, const float* __restrict__ xin,
                                __nv_bfloat16* __restrict__ xh, __nv_bfloat16* __restrict__ xl,
                                int M, int do_norm) {
    long long idx = (long long)blockIdx.x * blockDim.x + threadIdx.x;
    int row = (int)(idx >> 5);
    if (row >= M) return;
    int lane = (int)(idx & 31);
    int s = __ldg(rp + row), e = __ldg(rp + row + 1);
    float ax = 0.f, ay = 0.f, az = 0.f, aw = 0.f;
    for (int j = s; j < e; j++) {
        int c = __ldg(cs + j);
        float v = __ldg(vs + j);
        float4 xv = *(const float4*)(xin + (size_t)c * HH + lane * 4);
        ax += v * xv.x; ay += v * xv.y; az += v * xv.z; aw += v * xv.w;
    }
    ax = fmaxf(ax, 0.f); ay = fmaxf(ay, 0.f);
    az = fmaxf(az, 0.f); aw = fmaxf(aw, 0.f);
    if (do_norm) {
        float ss = ax * ax + ay * ay + az * az + aw * aw;
        #pragma unroll
        for (int o = 16; o; o >>= 1) ss += __shfl_xor_sync(0xffffffffu, ss, o);
        float inv = 1.0f / fmaxf(sqrtf(ss), 1e-12f);
        ax *= inv; ay *= inv; az *= inv; aw *= inv;
    }
    uint2 hv, lv;
    pack_hl(ax, ay, hv.x, lv.x);
    pack_hl(az, aw, hv.y, lv.y);
    size_t off = (size_t)row * HH + lane * 4;
    *(uint2*)(xh + off) = hv;
    *(uint2*)(xl + off) = lv;
}

__global__ void mul_kernel(const float* __restrict__ a, const float* __restrict__ b,
                           float* __restrict__ out, int M) {
    int i = blockIdx.x * blockDim.x + threadIdx.x;
    if (i < M) out[i] = a[i] * b[i];
}

// ---------------- pipelined mma.sync GEMM -------------------------------------
// 3-term Markidis bf16 split. BM=128,BN=128,BK=32; 8 warps (2x4).
// 4-stage cp.async pipeline, one __syncthreads per chunk, frag double-buffer.
// mode 0 (fused m1+w): blockIdx.y < ny1 -> B1 (m1), relu+bias1, split write Ch/Cl [Ncol1]
//                      blockIdx.y ==ny1 -> B2 (w), raw fp32 write C2 [Ncol2]
// mode 1 (m2 scoring): B1 (m2), epilogue relu(acc+bias1) dot m3s -> atomicAdd(sc)
#define BK 32
#define LDP 40
#define STG_ELEMS (128 * LDP)
#define NSTG 4
#define GEMM_SMEM (NSTG * 4 * STG_ELEMS * 2)   // 163840 B

__global__ void __launch_bounds__(256, 1) tc_gemm_kernel(
    const __nv_bfloat16* __restrict__ Ah, const __nv_bfloat16* __restrict__ Al,
    const __nv_bfloat16* __restrict__ B1h, const __nv_bfloat16* __restrict__ B1l,
    int ny1, int Ncol1, const float* __restrict__ bias1,
    const __nv_bfloat16* __restrict__ B2h, const __nv_bfloat16* __restrict__ B2l,
    float* __restrict__ C2, int Ncol2,
    __nv_bfloat16* __restrict__ Ch, __nv_bfloat16* __restrict__ Cl,
    const float* __restrict__ m3s, float* __restrict__ sc,
    int M, int K, int mode)
{
    extern __shared__ __align__(16) uint16_t smem[];
    const int tid = threadIdx.x;
    const int wid = tid >> 5, lane = tid & 31;
    const int mw = wid >> 2, nw = wid & 3;
    const int row0 = blockIdx.x * 128;
    const bool isW = (mode == 0) && ((int)blockIdx.y == ny1);
    const __nv_bfloat16* Bh = isW ? B2h : B1h;
    const __nv_bfloat16* Bl = isW ? B2l : B1l;
    const int n0 = isW ? 0 : blockIdx.y * 128;

    float acc[4][4][4] = {};
    const uint32_t sbase = smem_u32(smem);
    auto abase = [&](int stage, int arr) {
        return sbase + (uint32_t)(((stage << 2) + arr) * STG_ELEMS * 2);
    };

    auto load_chunk = [&](int c, int stage) {
        const int k0 = c * BK;
        #pragma unroll
        for (int i = 0; i < 2; i++) {
            int idx = tid + i * 256;
            int r = idx >> 2, q = idx & 3;
            uint32_t doff = (uint32_t)(r * LDP + q * 8) * 2;
            int grow = row0 + r;
            int pa = (grow < M) ? 16 : 0;
            int ga = grow < M ? grow : (M - 1);
            cpa16(abase(stage, 0) + doff, Ah + (size_t)ga * K + k0 + q * 8, pa);
            cpa16(abase(stage, 1) + doff, Al + (size_t)ga * K + k0 + q * 8, pa);
            cpa16(abase(stage, 2) + doff, Bh + (size_t)(n0 + r) * K + k0 + q * 8, 16);
            cpa16(abase(stage, 3) + doff, Bl + (size_t)(n0 + r) * K + k0 + q * 8, 16);
        }
    };

    const int a_row_sel = lane & 15;
    const int a_k_sel   = (lane >> 4) * 8;
    const int b_row_sel = (lane & 7) + ((lane >> 4) << 3);
    const int b_k_sel   = ((lane >> 3) & 1) * 8;

    uint32_t ah[2][4][4], al[2][4][4], bh[2][2][4], bl[2][2][4];
    auto load_frags = [&](int buf, uint32_t sAh, uint32_t sAl, uint32_t sBh,
                          uint32_t sBl, int koff) {
        #pragma unroll
        for (int mi = 0; mi < 4; mi++) {
            uint32_t off = (uint32_t)((mw * 64 + mi * 16 + a_row_sel) * LDP
                                      + koff + a_k_sel) * 2;
            ldmx4(ah[buf][mi], sAh + off);
            ldmx4(al[buf][mi], sAl + off);
        }
        #pragma unroll
        for (int p = 0; p < 2; p++) {
            uint32_t off = (uint32_t)((nw * 32 + p * 16 + b_row_sel) * LDP
                                      + koff + b_k_sel) * 2;
            ldmx4(bh[buf][p], sBh + off);
            ldmx4(bl[buf][p], sBl + off);
        }
    };
    auto run_mmas = [&](int buf) {
        #pragma unroll
        for (int mi = 0; mi < 4; mi++) {
            #pragma unroll
            for (int ni = 0; ni < 4; ni++) {
                uint32_t b0h = bh[buf][ni >> 1][(ni & 1) * 2];
                uint32_t b1h = bh[buf][ni >> 1][(ni & 1) * 2 + 1];
                uint32_t b0l = bl[buf][ni >> 1][(ni & 1) * 2];
                uint32_t b1l = bl[buf][ni >> 1][(ni & 1) * 2 + 1];
                mma_bf16(acc[mi][ni], ah[buf][mi], b0h, b1h);
                mma_bf16(acc[mi][ni], ah[buf][mi], b0l, b1l);
                mma_bf16(acc[mi][ni], al[buf][mi], b0h, b1h);
            }
        }
    };

    const int nchunks = K / BK;
    load_chunk(0, 0);
    asm volatile("cp.async.commit_group;" ::: "memory");
    if (nchunks > 1) load_chunk(1, 1);
    asm volatile("cp.async.commit_group;" ::: "memory");

    for (int c = 0; c < nchunks; c++) {
        if (c + 2 < nchunks) load_chunk(c + 2, (c + 2) & (NSTG - 1));
        asm volatile("cp.async.commit_group;" ::: "memory");
        asm volatile("cp.async.wait_group 2;" ::: "memory");
        __syncthreads();
        const int st = c & (NSTG - 1);
        const uint32_t sAh = abase(st, 0), sAl = abase(st, 1);
        const uint32_t sBh = abase(st, 2), sBl = abase(st, 3);
        load_frags(0, sAh, sAl, sBh, sBl, 0);
        load_frags(1, sAh, sAl, sBh, sBl, 16);
        run_mmas(0);
        run_mmas(1);
    }

    const int mrow = row0 + mw * 64 + (lane >> 2);
    const int ncol = nw * 32 + (lane & 3) * 2;   // local within 128-tile

    if (mode == 1) {  // fused scoring
        #pragma unroll
        for (int mi = 0; mi < 4; mi++) {
            int r_lo = mrow + mi * 16;
            int r_hi = r_lo + 8;
            float plo = 0.f, phi = 0.f;
            #pragma unroll
            for (int ni = 0; ni < 4; ni++) {
                int col = n0 + ncol + ni * 8;
                float m30 = __ldg(m3s + col), m31 = __ldg(m3s + col + 1);
                float b0 = __ldg(bias1 + col), b1 = __ldg(bias1 + col + 1);
                plo += fmaxf(acc[mi][ni][0] + b0, 0.f) * m30
                     + fmaxf(acc[mi][ni][1] + b1, 0.f) * m31;
                phi += fmaxf(acc[mi][ni][2] + b0, 0.f) * m30
                     + fmaxf(acc[mi][ni][3] + b1, 0.f) * m31;
            }
            plo += __shfl_xor_sync(0xffffffffu, plo, 1);
            plo += __shfl_xor_sync(0xffffffffu, plo, 2);
            phi += __shfl_xor_sync(0xffffffffu, phi, 1);
            phi += __shfl_xor_sync(0xffffffffu, phi, 2);
            if ((lane & 3) == 0) {
                if (r_lo < M) atomicAdd(sc + r_lo, plo);
                if (r_hi < M) atomicAdd(sc + r_hi, phi);
            }
        }
        return;
    }

    if (!isW) {  // m1 part: relu + bf16 hi/lo split write
        #pragma unroll
        for (int mi = 0; mi < 4; mi++) {
            int r_lo = mrow + mi * 16;
            int r_hi = r_lo + 8;
            #pragma unroll
            for (int ni = 0; ni < 4; ni++) {
                int col = n0 + ncol + ni * 8;
                float b0 = __ldg(bias1 + col), b1 = __ldg(bias1 + col + 1);
                float v0 = fmaxf(acc[mi][ni][0] + b0, 0.f);
                float v1 = fmaxf(acc[mi][ni][1] + b1, 0.f);
                float v2 = fmaxf(acc[mi][ni][2] + b0, 0.f);
                float v3 = fmaxf(acc[mi][ni][3] + b1, 0.f);
                uint32_t hu, lu;
                if (r_lo < M) {
                    pack_hl(v0, v1, hu, lu);
                    *(uint32_t*)(Ch + (size_t)r_lo * Ncol1 + col) = hu;
                    *(uint32_t*)(Cl + (size_t)r_lo * Ncol1 + col) = lu;
                }
                if (r_hi < M) {
                    pack_hl(v2, v3, hu, lu);
                    *(uint32_t*)(Ch + (size_t)r_hi * Ncol1 + col) = hu;
                    *(uint32_t*)(Cl + (size_t)r_hi * Ncol1 + col) = lu;
                }
            }
        }
        return;
    }

    // w part: raw fp32 write to C2
    #pragma unroll
    for (int mi = 0; mi < 4; mi++) {
        int r_lo = mrow + mi * 16;
        int r_hi = r_lo + 8;
        #pragma unroll
        for (int ni = 0; ni < 4; ni++) {
            int col = ncol + ni * 8;
            if (r_lo < M) *(float2*)(C2 + (size_t)r_lo * Ncol2 + col) =
                make_float2(acc[mi][ni][0], acc[mi][ni][1]);
            if (r_hi < M) *(float2*)(C2 + (size_t)r_hi * Ncol2 + col) =
                make_float2(acc[mi][ni][2], acc[mi][ni][3]);
        }
    }
}

// ---------------- launch -----------------------------------------------------
extern "C" void kernel_launch(void* const* d_in, const int* in_sizes, int n_in,
                              void* d_out, int out_size) {
    const int*   adjr[2] = {(const int*)d_in[0], (const int*)d_in[3]};
    const int*   adjc[2] = {(const int*)d_in[1], (const int*)d_in[4]};
    const float* adjv[2] = {(const float*)d_in[2], (const float*)d_in[5]};
    const float* w1 = (const float*)d_in[6];
    const float* m1 = (const float*)d_in[15];
    const float* b1 = (const float*)d_in[16];
    const float* m2 = (const float*)d_in[17];
    const float* b2 = (const float*)d_in[18];
    const float* m3 = (const float*)d_in[19];
    const float* b3 = (const float*)d_in[20];
    float* out = (float*)d_out;

    const int E = in_sizes[0];
    const int M = in_sizes[6] / HH;

    __nv_bfloat16 *xh, *xl, *h1h, *h1l, *wth, *wtl;
    float *gt, *csv;
    float (*gs)[NN];
    int *rp, *cnt, *csc;
    cudaGetSymbolAddress((void**)&xh,  g_xh);
    cudaGetSymbolAddress((void**)&xl,  g_xl);
    cudaGetSymbolAddress((void**)&gt,  g_t);
    cudaGetSymbolAddress((void**)&h1h, g_h1h);
    cudaGetSymbolAddress((void**)&h1l, g_h1l);
    cudaGetSymbolAddress((void**)&gs,  g_s);
    cudaGetSymbolAddress((void**)&rp,  g_rp);
    cudaGetSymbolAddress((void**)&cnt, g_cnt);
    cudaGetSymbolAddress((void**)&csc, g_cols);
    cudaGetSymbolAddress((void**)&csv, g_vals);
    cudaGetSymbolAddress((void**)&wth, g_wth);
    cudaGetSymbolAddress((void**)&wtl, g_wtl);

    cudaFuncSetAttribute(tc_gemm_kernel,
                         cudaFuncAttributeMaxDynamicSharedMemorySize, GEMM_SMEM);

    ConvSrcs cs;
    for (int i = 0; i < 8; i++) cs.p[i] = (const float*)d_in[7 + i];
    cs.p[8] = m1; cs.p[9] = m2;
    {
        int tot = (int)WT_TOTAL + NN;
        conv_all_kernel<<<(tot + 255) / 256, 256>>>(cs, wth, wtl, cnt);
    }

    const int warpBlocks = (int)(((long long)M * 32 + 255) / 256);
    const int eBlocks = (E + 255) / 256;
    const int nBlocks = (M + 255) / 256;
    const int mtiles = (M + 127) / 128;

    for (int b = 0; b < 2; b++) {
        if (b) zero_int_kernel<<<nBlocks, 256>>>(cnt, M);
        hist_kernel<<<eBlocks, 256>>>(adjr[b], cnt, E);
        scan_kernel<<<1, 1024>>>(cnt, rp, cnt, M);
        scatter_kernel<<<eBlocks, 256>>>(adjr[b], adjc[b], adjv[b], cnt, csc, csv,
                                         E, gs[b], b3, M);
        spmm_csr_kernel<<<warpBlocks, 256>>>(rp, csc, csv, w1, xh, xl, M, 1);

        for (int L = 0; L <= 8; L++) {
            // fused m1 (+ wL when L<8): A = x
            dim3 gf(mtiles, (L < 8) ? 3 : 2);
            tc_gemm_kernel<<<gf, 256, GEMM_SMEM>>>(
                xh, xl,
                wth + WT_M1, wtl + WT_M1, 2, HD2, b1,
                (L < 8) ? wth + WT_W(L) : nullptr,
                (L < 8) ? wtl + WT_W(L) : nullptr, gt, HH,
                h1h, h1l, nullptr, nullptr, M, HH, 0);
            // m2 scoring
            dim3 gm(mtiles, 2);
            tc_gemm_kernel<<<gm, 256, GEMM_SMEM>>>(
                h1h, h1l,
                wth + WT_M2, wtl + WT_M2, 2, HD2, b2,
                nullptr, nullptr, nullptr, 0,
                nullptr, nullptr, m3, gs[b], M, HD2, 1);
            if (L < 8)
                spmm_csr_kernel<<<warpBlocks, 256>>>(rp, csc, csv, gt, xh, xl, M,
                                                     (L + 1 < 8) ? 1 : 0);
        }
    }

    mul_kernel<<<nBlocks, 256>>>(gs[0], gs[1], out, M);
}